// round 4
// baseline (speedup 1.0000x reference)
#include <cuda_runtime.h>
#include <math.h>
#include <stdint.h>

#define NT 1024
#define NV 128
#define NXS 512
#define NVX 65536          // NV*NXS (contraction length of GEMM1)
#define KDIM 257
#define KP 288             // padded KDIM (2 x 144)
#define NXOUT 2048

// -------- scratch (no allocations allowed) --------
__device__ float g_psiT[(size_t)KP * NVX];    // transposed psi * (hx*hv), tf32-rounded
__device__ float g_w[(size_t)NT * KP];        // weights accumulator
__device__ float g_phi[(size_t)KP * NXOUT];   // fourier basis (rows >= 257 zero)

// ============================ helpers ============================
__device__ __forceinline__ uint32_t smem_u32(const void* p) {
    uint32_t a;
    asm("{ .reg .u64 t; cvta.to.shared.u64 t, %1; cvt.u32.u64 %0, t; }" : "=r"(a) : "l"(p));
    return a;
}
__device__ __forceinline__ uint32_t rna_tf32(float x) {
    uint32_t r;
    asm("cvt.rna.tf32.f32 %0, %1;" : "=r"(r) : "f"(x));
    return r;
}
__device__ __forceinline__ void mma_tf32(float* c, const uint32_t* a, uint32_t b0, uint32_t b1) {
    asm volatile(
        "mma.sync.aligned.m16n8k8.row.col.f32.tf32.tf32.f32 "
        "{%0,%1,%2,%3}, {%4,%5,%6,%7}, {%8,%9}, {%0,%1,%2,%3};"
        : "+f"(c[0]), "+f"(c[1]), "+f"(c[2]), "+f"(c[3])
        : "r"(a[0]), "r"(a[1]), "r"(a[2]), "r"(a[3]), "r"(b0), "r"(b1));
}
__device__ __forceinline__ void cp_async16(uint32_t dst, const void* src) {
    asm volatile("cp.async.ca.shared.global [%0], [%1], 16;" :: "r"(dst), "l"(src) : "memory");
}
__device__ __forceinline__ void cp_commit() { asm volatile("cp.async.commit_group;" ::: "memory"); }
__device__ __forceinline__ void cp_wait0()  { asm volatile("cp.async.wait_group 0;" ::: "memory"); }

// ---------------- Psi MLP: (x,v) -> 257, transposed + scaled + tf32-rounded ----------------
__global__ void psi_kernel(const float* __restrict__ xs, const float* __restrict__ vs,
                           const float* __restrict__ W1, const float* __restrict__ b1,
                           const float* __restrict__ W2, const float* __restrict__ b2,
                           const float* __restrict__ W3, const float* __restrict__ b3)
{
    __shared__ float sW1[128];
    __shared__ float sb1[64];
    __shared__ float sW2[64 * 32];
    __shared__ float sb2[32];
    __shared__ float sW3[32 * KDIM];
    __shared__ float sb3[KDIM];

    int tid = threadIdx.x;
    for (int i = tid; i < 128; i += 256)       sW1[i] = W1[i];
    for (int i = tid; i < 64; i += 256)        sb1[i] = b1[i];
    for (int i = tid; i < 64 * 32; i += 256)   sW2[i] = W2[i];
    if (tid < 32)                              sb2[tid] = b2[tid];
    for (int i = tid; i < 32 * KDIM; i += 256) sW3[i] = W3[i];
    for (int i = tid; i < KDIM; i += 256)      sb3[i] = b3[i];
    __syncthreads();

    int p = blockIdx.x * 256 + tid;
    int v = p >> 9;
    int x = p & 511;
    float xin = xs[x];
    float vin = vs[v];
    float scale = (xs[1] - xs[0]) * (vs[1] - vs[0]);   // hx * hv

    float h1[64];
#pragma unroll
    for (int j = 0; j < 64; j++) {
        float s = fmaf(xin, sW1[j], fmaf(vin, sW1[64 + j], sb1[j]));
        h1[j] = fmaxf(s, 0.0f);
    }
    float h2[32];
#pragma unroll
    for (int j = 0; j < 32; j++) {
        float s = sb2[j];
#pragma unroll
        for (int i = 0; i < 64; i++) s = fmaf(h1[i], sW2[i * 32 + j], s);
        h2[j] = fmaxf(s, 0.0f);
    }
    for (int k = 0; k < KDIM; k++) {
        float s = sb3[k];
#pragma unroll
        for (int j = 0; j < 32; j++) s = fmaf(h2[j], sW3[j * KDIM + k], s);
        g_psiT[(size_t)k * NVX + p] = __uint_as_float(rna_tf32(s * scale));
    }
}

// ---------------- zero g_w + padding rows of psiT/phi ----------------
#define ZERO_TOTAL (NT * KP + (KP - KDIM) * NVX + (KP - KDIM) * NXOUT)
__global__ void zero_misc_kernel()
{
    int i = blockIdx.x * 256 + threadIdx.x;
    if (i < NT * KP) { g_w[i] = 0.0f; return; }
    i -= NT * KP;
    if (i < (KP - KDIM) * NVX) { g_psiT[(size_t)KDIM * NVX + i] = 0.0f; return; }
    i -= (KP - KDIM) * NVX;
    if (i < (KP - KDIM) * NXOUT) g_phi[(size_t)KDIM * NXOUT + i] = 0.0f;
}

// ---------------- phi table: (K, Nx_out) ----------------
__global__ void phi_kernel(const float* __restrict__ x_out, const float* __restrict__ xs)
{
    int idx = blockIdx.x * 256 + threadIdx.x;
    if (idx >= KDIM * NXOUT) return;
    int r = idx / NXOUT;
    int x = idx - r * NXOUT;
    float w = (2.0f * 3.14159265358979323846f) / (xs[NXS - 1] - xs[0]);
    float xo = x_out[x];
    float val;
    if (r < 128) val = sinf((float)(r + 1) * w * xo);
    else         val = cosf((float)(r - 128) * w * xo);
    g_phi[idx] = val;
}

// ---------------- GEMM1 via mma.sync tf32 ----------------
// C (1024 x 288) += f (1024 x 65536) @ psiT^T
// CTA tile 256x144, BK=32, 512 threads: warps 8(M) x 2(N), warp tile 32x72, split-K 16.
#define BM 256
#define BN 144
#define BK 32
#define SPLITS 16
#define KCHUNK (NVX / SPLITS)    // 4096
#define NIT (KCHUNK / BK)        // 128
#define SA 36                    // float stride per row: bank = (4q+j)%32, conflict-free
#define SB 36
#define A_FLOATS (BM * SA)       // 9216 per stage
#define B_FLOATS (BN * SB)       // 5184 per stage
#define SMEM_FLOATS (2 * A_FLOATS + 2 * B_FLOATS)   // 28800 floats = 115200 B
#define B_VEC (BN * 8)           // 1152 float4 loads per B tile

__global__ void __launch_bounds__(512, 1) gemm1_mma(const float* __restrict__ f)
{
    extern __shared__ __align__(16) float sm[];
    float* As[2] = { sm, sm + A_FLOATS };
    float* Bs[2] = { sm + 2 * A_FLOATS, sm + 2 * A_FLOATS + B_FLOATS };
    uint32_t sm_b = smem_u32(sm);
    uint32_t bs_u32[2] = { sm_b + 2 * A_FLOATS * 4, sm_b + (2 * A_FLOATS + B_FLOATS) * 4 };

    const int tid = threadIdx.x;
    const int lane = tid & 31;
    const int warp = tid >> 5;               // 0..15
    const int wm = warp & 7;                 // 0..7 (M)
    const int wn = warp >> 3;                // 0..1 (N)
    const int q = lane >> 2, j = lane & 3;

    const int row0 = blockIdx.y * BM;
    const int col0 = blockIdx.x * BN;
    const size_t kb0 = (size_t)blockIdx.z * KCHUNK;

    const int lrow = tid >> 3;               // 0..63
    const int loct = tid & 7;                // 0..7

    float acc[2][9][4];
#pragma unroll
    for (int a = 0; a < 2; a++)
#pragma unroll
        for (int b = 0; b < 9; b++)
#pragma unroll
            for (int c = 0; c < 4; c++) acc[a][b][c] = 0.0f;

    // ---- prologue: fill stage 0 ----
    {
#pragma unroll
        for (int p = 0; p < 3; p++) {
            int idx = tid + p * 512;
            if (idx < B_VEC) {
                int r = idx >> 3, o = idx & 7;
                cp_async16(bs_u32[0] + (uint32_t)(r * SB + o * 4) * 4,
                           g_psiT + (size_t)(col0 + r) * NVX + kb0 + o * 4);
            }
        }
        cp_commit();
#pragma unroll
        for (int i = 0; i < 4; i++) {
            int r = lrow + i * 64;
            float4 v = *(const float4*)(f + (size_t)(row0 + r) * NVX + kb0 + loct * 4);
            uint4 u;
            u.x = rna_tf32(v.x); u.y = rna_tf32(v.y); u.z = rna_tf32(v.z); u.w = rna_tf32(v.w);
            *(uint4*)(As[0] + r * SA + loct * 4) = u;
        }
        cp_wait0();
        __syncthreads();
    }

    float4 av[4];
    for (int it = 0; it < NIT; ++it) {
        const int s = it & 1;
        const bool pf = (it + 1 < NIT);
        const size_t kb = kb0 + (size_t)(it + 1) * BK;

        if (pf) {
#pragma unroll
            for (int p = 0; p < 3; p++) {
                int idx = tid + p * 512;
                if (idx < B_VEC) {
                    int r = idx >> 3, o = idx & 7;
                    cp_async16(bs_u32[s ^ 1] + (uint32_t)(r * SB + o * 4) * 4,
                               g_psiT + (size_t)(col0 + r) * NVX + kb + o * 4);
                }
            }
            cp_commit();
#pragma unroll
            for (int i = 0; i < 4; i++)
                av[i] = *(const float4*)(f + (size_t)(row0 + lrow + i * 64) * NVX + kb + loct * 4);
        }

        // ---- compute 4 k8-steps on stage s ----
        const float* Ab = As[s];
        const float* Bb = Bs[s];
#pragma unroll
        for (int kk = 0; kk < 4; kk++) {
            uint32_t afr[2][4];
#pragma unroll
            for (int mt = 0; mt < 2; mt++) {
                const float* ap = Ab + (wm * 32 + mt * 16 + q) * SA + kk * 8 + j;
                afr[mt][0] = __float_as_uint(ap[0]);
                afr[mt][1] = __float_as_uint(ap[8 * SA]);
                afr[mt][2] = __float_as_uint(ap[4]);
                afr[mt][3] = __float_as_uint(ap[8 * SA + 4]);
            }
#pragma unroll
            for (int nt = 0; nt < 9; nt++) {
                const float* bp = Bb + (wn * 72 + nt * 8 + q) * SB + kk * 8 + j;
                uint32_t b0 = __float_as_uint(bp[0]);
                uint32_t b1 = __float_as_uint(bp[4]);
#pragma unroll
                for (int mt = 0; mt < 2; mt++)
                    mma_tf32(acc[mt][nt], afr[mt], b0, b1);
            }
        }

        if (pf) {
#pragma unroll
            for (int i = 0; i < 4; i++) {
                uint4 u;
                u.x = rna_tf32(av[i].x); u.y = rna_tf32(av[i].y);
                u.z = rna_tf32(av[i].z); u.w = rna_tf32(av[i].w);
                *(uint4*)(As[s ^ 1] + (lrow + i * 64) * SA + loct * 4) = u;
            }
            cp_wait0();
        }
        __syncthreads();
    }

    // ---- epilogue: atomic accumulate into g_w ----
#pragma unroll
    for (int mt = 0; mt < 2; mt++) {
        int r0 = row0 + wm * 32 + mt * 16 + q;
#pragma unroll
        for (int nt = 0; nt < 9; nt++) {
            int c0 = col0 + wn * 72 + nt * 8 + 2 * j;
            atomicAdd(&g_w[(size_t)r0 * KP + c0],           acc[mt][nt][0]);
            atomicAdd(&g_w[(size_t)r0 * KP + c0 + 1],       acc[mt][nt][1]);
            atomicAdd(&g_w[(size_t)(r0 + 8) * KP + c0],     acc[mt][nt][2]);
            atomicAdd(&g_w[(size_t)(r0 + 8) * KP + c0 + 1], acc[mt][nt][3]);
        }
    }
}

// ---------------- GEMM2: out = g_w (NT x KP) @ g_phi (KP x NXOUT) ----------------
#define G2_BM 64
#define G2_BN 64
#define G2_BK 16

__global__ void gemm2_kernel(float* __restrict__ out)
{
    __shared__ __align__(16) float As2[G2_BK][G2_BM + 4];
    __shared__ __align__(16) float Bs2[G2_BK][G2_BN];

    int nt = blockIdx.x;
    int mt = blockIdx.y;
    int tid = threadIdx.x;
    int tx = tid & 15;
    int ty = tid >> 4;

    int row0 = mt * G2_BM;
    int col0 = nt * G2_BN;

    float acc[4][4];
#pragma unroll
    for (int r = 0; r < 4; r++)
#pragma unroll
        for (int c = 0; c < 4; c++) acc[r][c] = 0.0f;

    for (int kc = 0; kc < KP; kc += G2_BK) {
#pragma unroll
        for (int i = 0; i < 4; i++) {
            int l = tid + i * 256;
            int mrow = l >> 4;
            int kk = l & 15;
            As2[kk][mrow] = g_w[(size_t)(row0 + mrow) * KP + kc + kk];
        }
#pragma unroll
        for (int i = 0; i < 4; i++) {
            int l = tid + i * 256;
            int kk = l >> 6;
            int n = l & 63;
            Bs2[kk][n] = g_phi[(size_t)(kc + kk) * NXOUT + col0 + n];
        }
        __syncthreads();
#pragma unroll
        for (int kk = 0; kk < G2_BK; kk++) {
            float4 a = *(const float4*)&As2[kk][ty * 4];
            float4 b = *(const float4*)&Bs2[kk][tx * 4];
            float avv[4] = {a.x, a.y, a.z, a.w};
            float bvv[4] = {b.x, b.y, b.z, b.w};
#pragma unroll
            for (int r = 0; r < 4; r++)
#pragma unroll
                for (int c = 0; c < 4; c++)
                    acc[r][c] = fmaf(avv[r], bvv[c], acc[r][c]);
        }
        __syncthreads();
    }

#pragma unroll
    for (int r = 0; r < 4; r++) {
        int gm = row0 + ty * 4 + r;
#pragma unroll
        for (int c = 0; c < 4; c++) {
            int gn = col0 + tx * 4 + c;
            out[(size_t)gm * NXOUT + gn] = acc[r][c];
        }
    }
}

extern "C" void kernel_launch(void* const* d_in, const int* in_sizes, int n_in,
                              void* d_out, int out_size)
{
    const float* x_out = (const float*)d_in[0];
    const float* f     = (const float*)d_in[1];
    const float* xs    = (const float*)d_in[2];
    const float* vs    = (const float*)d_in[3];
    const float* W1    = (const float*)d_in[4];
    const float* b1    = (const float*)d_in[5];
    const float* W2    = (const float*)d_in[6];
    const float* b2    = (const float*)d_in[7];
    const float* W3    = (const float*)d_in[8];
    const float* b3    = (const float*)d_in[9];
    float* out = (float*)d_out;

    static int smem_set = 0;
    if (!smem_set) {
        cudaFuncSetAttribute(gemm1_mma, cudaFuncAttributeMaxDynamicSharedMemorySize,
                             SMEM_FLOATS * 4);
        smem_set = 1;
    }

    psi_kernel<<<NVX / 256, 256>>>(xs, vs, W1, b1, W2, b2, W3, b3);
    zero_misc_kernel<<<(ZERO_TOTAL + 255) / 256, 256>>>();
    phi_kernel<<<(KDIM * NXOUT + 255) / 256, 256>>>(x_out, xs);
    {
        dim3 grid(2, 4, SPLITS);   // N tiles, M tiles, split-K
        gemm1_mma<<<grid, 512, SMEM_FLOATS * 4>>>(f);
    }
    {
        dim3 grid(NXOUT / G2_BN, NT / G2_BM);
        gemm2_kernel<<<grid, 256>>>(out);
    }
}

// round 5
// speedup vs baseline: 1.1951x; 1.1951x over previous
#include <cuda_runtime.h>
#include <math.h>
#include <stdint.h>

#define NT 1024
#define NV 128
#define NXS 512
#define NVX 65536          // NV*NXS (contraction length of GEMM1)
#define KDIM 257
#define KP 288             // padded KDIM (2 x 144)
#define NXOUT 2048

// -------- scratch (no allocations allowed) --------
__device__ float g_psiT[(size_t)KP * NVX];    // transposed psi * (hx*hv), tf32-rounded
__device__ float g_w[(size_t)NT * KP];        // weights accumulator
__device__ float g_phi[(size_t)KP * NXOUT];   // fourier basis (rows >= 257 zero)

// ============================ helpers ============================
__device__ __forceinline__ uint32_t smem_u32(const void* p) {
    uint32_t a;
    asm("{ .reg .u64 t; cvta.to.shared.u64 t, %1; cvt.u32.u64 %0, t; }" : "=r"(a) : "l"(p));
    return a;
}
__device__ __forceinline__ uint32_t rna_tf32(float x) {
    uint32_t r;
    asm("cvt.rna.tf32.f32 %0, %1;" : "=r"(r) : "f"(x));
    return r;
}
__device__ __forceinline__ void mma_tf32(float* c, const uint32_t* a, uint32_t b0, uint32_t b1) {
    asm volatile(
        "mma.sync.aligned.m16n8k8.row.col.f32.tf32.tf32.f32 "
        "{%0,%1,%2,%3}, {%4,%5,%6,%7}, {%8,%9}, {%0,%1,%2,%3};"
        : "+f"(c[0]), "+f"(c[1]), "+f"(c[2]), "+f"(c[3])
        : "r"(a[0]), "r"(a[1]), "r"(a[2]), "r"(a[3]), "r"(b0), "r"(b1));
}
__device__ __forceinline__ void cp_async16(uint32_t dst, const void* src) {
    asm volatile("cp.async.ca.shared.global [%0], [%1], 16;" :: "r"(dst), "l"(src) : "memory");
}
__device__ __forceinline__ void cp_commit() { asm volatile("cp.async.commit_group;" ::: "memory"); }
__device__ __forceinline__ void cp_wait0()  { asm volatile("cp.async.wait_group 0;" ::: "memory"); }

// ---------------- Psi MLP: (x,v) -> 257, transposed + scaled + tf32-rounded ----------------
__global__ void psi_kernel(const float* __restrict__ xs, const float* __restrict__ vs,
                           const float* __restrict__ W1, const float* __restrict__ b1,
                           const float* __restrict__ W2, const float* __restrict__ b2,
                           const float* __restrict__ W3, const float* __restrict__ b3)
{
    __shared__ float sW1[128];
    __shared__ float sb1[64];
    __shared__ float sW2[64 * 32];
    __shared__ float sb2[32];
    __shared__ float sW3[32 * KDIM];
    __shared__ float sb3[KDIM];

    int tid = threadIdx.x;
    for (int i = tid; i < 128; i += 256)       sW1[i] = W1[i];
    for (int i = tid; i < 64; i += 256)        sb1[i] = b1[i];
    for (int i = tid; i < 64 * 32; i += 256)   sW2[i] = W2[i];
    if (tid < 32)                              sb2[tid] = b2[tid];
    for (int i = tid; i < 32 * KDIM; i += 256) sW3[i] = W3[i];
    for (int i = tid; i < KDIM; i += 256)      sb3[i] = b3[i];
    __syncthreads();

    int p = blockIdx.x * 256 + tid;
    int v = p >> 9;
    int x = p & 511;
    float xin = xs[x];
    float vin = vs[v];
    float scale = (xs[1] - xs[0]) * (vs[1] - vs[0]);   // hx * hv

    float h1[64];
#pragma unroll
    for (int j = 0; j < 64; j++) {
        float s = fmaf(xin, sW1[j], fmaf(vin, sW1[64 + j], sb1[j]));
        h1[j] = fmaxf(s, 0.0f);
    }
    float h2[32];
#pragma unroll
    for (int j = 0; j < 32; j++) {
        float s = sb2[j];
#pragma unroll
        for (int i = 0; i < 64; i++) s = fmaf(h1[i], sW2[i * 32 + j], s);
        h2[j] = fmaxf(s, 0.0f);
    }
    for (int k = 0; k < KDIM; k++) {
        float s = sb3[k];
#pragma unroll
        for (int j = 0; j < 32; j++) s = fmaf(h2[j], sW3[j * KDIM + k], s);
        g_psiT[(size_t)k * NVX + p] = __uint_as_float(rna_tf32(s * scale));
    }
}

// ---------------- zero g_w + padding rows of psiT/phi ----------------
#define ZERO_TOTAL (NT * KP + (KP - KDIM) * NVX + (KP - KDIM) * NXOUT)
__global__ void zero_misc_kernel()
{
    int i = blockIdx.x * 256 + threadIdx.x;
    if (i < NT * KP) { g_w[i] = 0.0f; return; }
    i -= NT * KP;
    if (i < (KP - KDIM) * NVX) { g_psiT[(size_t)KDIM * NVX + i] = 0.0f; return; }
    i -= (KP - KDIM) * NVX;
    if (i < (KP - KDIM) * NXOUT) g_phi[(size_t)KDIM * NXOUT + i] = 0.0f;
}

// ---------------- phi table: (K, Nx_out) ----------------
__global__ void phi_kernel(const float* __restrict__ x_out, const float* __restrict__ xs)
{
    int idx = blockIdx.x * 256 + threadIdx.x;
    if (idx >= KDIM * NXOUT) return;
    int r = idx / NXOUT;
    int x = idx - r * NXOUT;
    float w = (2.0f * 3.14159265358979323846f) / (xs[NXS - 1] - xs[0]);
    float xo = x_out[x];
    float val;
    if (r < 128) val = sinf((float)(r + 1) * w * xo);
    else         val = cosf((float)(r - 128) * w * xo);
    g_phi[idx] = val;
}

// ---------------- GEMM1 via mma.sync tf32 ----------------
// C (1024 x 288) += f (1024 x 65536) @ psiT^T
// CTA tile 256x144, BK=32, 256 threads: warps 4(M) x 2(N), warp tile 64x72, split-K 16.
#define BM 256
#define BN 144
#define BK 32
#define SPLITS 16
#define KCHUNK (NVX / SPLITS)    // 4096
#define NIT (KCHUNK / BK)        // 128
#define SA 36                    // bank = (4q+j)%32 -> conflict-free fragment access
#define SB 36
#define A_FLOATS (BM * SA)       // 9216 per stage
#define B_FLOATS (BN * SB)       // 5184 per stage
#define SMEM_FLOATS (2 * A_FLOATS + 2 * B_FLOATS)   // 28800 floats = 115200 B

__global__ void __launch_bounds__(256, 1) gemm1_mma(const float* __restrict__ f)
{
    extern __shared__ __align__(16) float sm[];
    float* As[2] = { sm, sm + A_FLOATS };
    float* Bs[2] = { sm + 2 * A_FLOATS, sm + 2 * A_FLOATS + B_FLOATS };
    uint32_t sm_b = smem_u32(sm);
    uint32_t bs_u32[2] = { sm_b + 2 * A_FLOATS * 4, sm_b + (2 * A_FLOATS + B_FLOATS) * 4 };

    const int tid = threadIdx.x;
    const int lane = tid & 31;
    const int warp = tid >> 5;
    const int wm = warp & 3;                 // 0..3 (M)
    const int wn = warp >> 2;                // 0..1 (N)
    const int q = lane >> 2, j = lane & 3;

    const int row0 = blockIdx.y * BM;
    const int col0 = blockIdx.x * BN;
    const size_t kb0 = (size_t)blockIdx.z * KCHUNK;

    const int lrow = tid >> 3;               // 0..31
    const int loct = tid & 7;                // 0..7

    float acc[4][9][4];
#pragma unroll
    for (int a = 0; a < 4; a++)
#pragma unroll
        for (int b = 0; b < 9; b++)
#pragma unroll
            for (int c = 0; c < 4; c++) acc[a][b][c] = 0.0f;

    // ---- prologue: fill stage 0 ----
    {
        // B via cp.async
#pragma unroll
        for (int i = 0; i < 5; i++) {
            int idx = tid + i * 256;
            if (idx < BN * 8) {
                int r = idx >> 3, o = idx & 7;
                cp_async16(bs_u32[0] + (uint32_t)(r * SB + o * 4) * 4,
                           g_psiT + (size_t)(col0 + r) * NVX + kb0 + o * 4);
            }
        }
        cp_commit();
        // A manual with cvt
#pragma unroll
        for (int i = 0; i < 8; i++) {
            float4 v = *(const float4*)(f + (size_t)(row0 + lrow + i * 32) * NVX + kb0 + loct * 4);
            uint4 u;
            u.x = rna_tf32(v.x); u.y = rna_tf32(v.y); u.z = rna_tf32(v.z); u.w = rna_tf32(v.w);
            *(uint4*)(As[0] + (lrow + i * 32) * SA + loct * 4) = u;
        }
        cp_wait0();
        __syncthreads();
    }

    float4 av[8];
    for (int it = 0; it < NIT; ++it) {
        const int s = it & 1;
        const bool pf = (it + 1 < NIT);
        const size_t kb = kb0 + (size_t)(it + 1) * BK;

        if (pf) {
            // B -> stage s^1 via cp.async
#pragma unroll
            for (int i = 0; i < 5; i++) {
                int idx = tid + i * 256;
                if (idx < BN * 8) {
                    int r = idx >> 3, o = idx & 7;
                    cp_async16(bs_u32[s ^ 1] + (uint32_t)(r * SB + o * 4) * 4,
                               g_psiT + (size_t)(col0 + r) * NVX + kb + o * 4);
                }
            }
            cp_commit();
            // A -> regs
#pragma unroll
            for (int i = 0; i < 8; i++)
                av[i] = *(const float4*)(f + (size_t)(row0 + lrow + i * 32) * NVX + kb + loct * 4);
        }

        // ---- compute 4 k8-steps on stage s ----
        const float* Ab = As[s];
        const float* Bb = Bs[s];
#pragma unroll
        for (int kk = 0; kk < 4; kk++) {
            uint32_t afr[4][4];
#pragma unroll
            for (int mt = 0; mt < 4; mt++) {
                const float* ap = Ab + (wm * 64 + mt * 16 + q) * SA + kk * 8 + j;
                afr[mt][0] = __float_as_uint(ap[0]);
                afr[mt][1] = __float_as_uint(ap[8 * SA]);
                afr[mt][2] = __float_as_uint(ap[4]);
                afr[mt][3] = __float_as_uint(ap[8 * SA + 4]);
            }
#pragma unroll
            for (int nt = 0; nt < 9; nt++) {
                const float* bp = Bb + (wn * 72 + nt * 8 + q) * SB + kk * 8 + j;
                uint32_t b0 = __float_as_uint(bp[0]);
                uint32_t b1 = __float_as_uint(bp[4]);
#pragma unroll
                for (int mt = 0; mt < 4; mt++)
                    mma_tf32(acc[mt][nt], afr[mt], b0, b1);
            }
        }

        if (pf) {
#pragma unroll
            for (int i = 0; i < 8; i++) {
                uint4 u;
                u.x = rna_tf32(av[i].x); u.y = rna_tf32(av[i].y);
                u.z = rna_tf32(av[i].z); u.w = rna_tf32(av[i].w);
                *(uint4*)(As[s ^ 1] + (lrow + i * 32) * SA + loct * 4) = u;
            }
            cp_wait0();
        }
        __syncthreads();
    }

    // ---- epilogue: atomic accumulate into g_w ----
#pragma unroll
    for (int mt = 0; mt < 4; mt++) {
        int r0 = row0 + wm * 64 + mt * 16 + q;
#pragma unroll
        for (int nt = 0; nt < 9; nt++) {
            int c0 = col0 + wn * 72 + nt * 8 + 2 * j;
            atomicAdd(&g_w[(size_t)r0 * KP + c0],           acc[mt][nt][0]);
            atomicAdd(&g_w[(size_t)r0 * KP + c0 + 1],       acc[mt][nt][1]);
            atomicAdd(&g_w[(size_t)(r0 + 8) * KP + c0],     acc[mt][nt][2]);
            atomicAdd(&g_w[(size_t)(r0 + 8) * KP + c0 + 1], acc[mt][nt][3]);
        }
    }
}

// ---------------- GEMM2: out = g_w (NT x KP) @ g_phi (KP x NXOUT) ----------------
#define G2_BM 64
#define G2_BN 64
#define G2_BK 16

__global__ void gemm2_kernel(float* __restrict__ out)
{
    __shared__ __align__(16) float As2[G2_BK][G2_BM + 4];
    __shared__ __align__(16) float Bs2[G2_BK][G2_BN];

    int nt = blockIdx.x;
    int mt = blockIdx.y;
    int tid = threadIdx.x;
    int tx = tid & 15;
    int ty = tid >> 4;

    int row0 = mt * G2_BM;
    int col0 = nt * G2_BN;

    float acc[4][4];
#pragma unroll
    for (int r = 0; r < 4; r++)
#pragma unroll
        for (int c = 0; c < 4; c++) acc[r][c] = 0.0f;

    for (int kc = 0; kc < KP; kc += G2_BK) {
#pragma unroll
        for (int i = 0; i < 4; i++) {
            int l = tid + i * 256;
            int mrow = l >> 4;
            int kk = l & 15;
            As2[kk][mrow] = g_w[(size_t)(row0 + mrow) * KP + kc + kk];
        }
#pragma unroll
        for (int i = 0; i < 4; i++) {
            int l = tid + i * 256;
            int kk = l >> 6;
            int n = l & 63;
            Bs2[kk][n] = g_phi[(size_t)(kc + kk) * NXOUT + col0 + n];
        }
        __syncthreads();
#pragma unroll
        for (int kk = 0; kk < G2_BK; kk++) {
            float4 a = *(const float4*)&As2[kk][ty * 4];
            float4 b = *(const float4*)&Bs2[kk][tx * 4];
            float avv[4] = {a.x, a.y, a.z, a.w};
            float bvv[4] = {b.x, b.y, b.z, b.w};
#pragma unroll
            for (int r = 0; r < 4; r++)
#pragma unroll
                for (int c = 0; c < 4; c++)
                    acc[r][c] = fmaf(avv[r], bvv[c], acc[r][c]);
        }
        __syncthreads();
    }

#pragma unroll
    for (int r = 0; r < 4; r++) {
        int gm = row0 + ty * 4 + r;
#pragma unroll
        for (int c = 0; c < 4; c++) {
            int gn = col0 + tx * 4 + c;
            out[(size_t)gm * NXOUT + gn] = acc[r][c];
        }
    }
}

extern "C" void kernel_launch(void* const* d_in, const int* in_sizes, int n_in,
                              void* d_out, int out_size)
{
    const float* x_out = (const float*)d_in[0];
    const float* f     = (const float*)d_in[1];
    const float* xs    = (const float*)d_in[2];
    const float* vs    = (const float*)d_in[3];
    const float* W1    = (const float*)d_in[4];
    const float* b1    = (const float*)d_in[5];
    const float* W2    = (const float*)d_in[6];
    const float* b2    = (const float*)d_in[7];
    const float* W3    = (const float*)d_in[8];
    const float* b3    = (const float*)d_in[9];
    float* out = (float*)d_out;

    static int smem_set = 0;
    if (!smem_set) {
        cudaFuncSetAttribute(gemm1_mma, cudaFuncAttributeMaxDynamicSharedMemorySize,
                             SMEM_FLOATS * 4);
        smem_set = 1;
    }

    psi_kernel<<<NVX / 256, 256>>>(xs, vs, W1, b1, W2, b2, W3, b3);
    zero_misc_kernel<<<(ZERO_TOTAL + 255) / 256, 256>>>();
    phi_kernel<<<(KDIM * NXOUT + 255) / 256, 256>>>(x_out, xs);
    {
        dim3 grid(2, 4, SPLITS);   // N tiles, M tiles, split-K
        gemm1_mma<<<grid, 256, SMEM_FLOATS * 4>>>(f);
    }
    {
        dim3 grid(NXOUT / G2_BN, NT / G2_BM);
        gemm2_kernel<<<grid, 256>>>(out);
    }
}